// round 12
// baseline (speedup 1.0000x reference)
#include <cuda_runtime.h>
#include <cuda_bf16.h>
#include <math.h>

// Problem constants
#define B_  8
#define T_  1024
#define D_  512
#define H_  8
#define HD_ 64
#define DFF_ 1024
#define DPR_ 32
#define ROWS_ (B_*T_)   // 8192

// ---------------- scratch (device globals; no allocation allowed) ----------------
__device__ float g_h   [ROWS_*D_];        // ln1 output (tf32-rounded)
__device__ float g_qkv [ROWS_*3*D_];      // qkv projection (full fp32)
__device__ float g_q   [B_*H_*T_*HD_];    // [B,H,T,HD] (tf32-rounded)
__device__ float g_k   [B_*H_*T_*HD_];    // (tf32-rounded)
__device__ float g_v   [B_*H_*T_*HD_];    // (tf32-rounded)
__device__ float g_ao  [B_*H_*T_*HD_];    // attention out (full fp32)
__device__ float g_xres[ROWS_*D_];        // x_value + attn (full fp32)
__device__ float g_h2  [ROWS_*D_];        // ln2 output (tf32-rounded)
__device__ float g_g   [ROWS_*DFF_];      // swiglu output (tf32-rounded)
__device__ float g_wa  [D_*3*D_];         // W_attn tf32-rounded
__device__ float g_w1  [D_*2*DFF_];       // W1 tf32-rounded
__device__ float g_w2  [DFF_*D_];         // W2 tf32-rounded

// ---------------- helpers ----------------
__device__ __forceinline__ void cpasync16(unsigned s, const void* g) {
    asm volatile("cp.async.cg.shared.global [%0], [%1], 16;" :: "r"(s), "l"(g));
}
__device__ __forceinline__ void cpcommit() {
    asm volatile("cp.async.commit_group;");
}
__device__ __forceinline__ unsigned rna_tf32f(float f) {
    unsigned r;
    asm("cvt.rna.tf32.f32 %0, %1;" : "=r"(r) : "f"(f));
    return r;
}
__device__ __forceinline__ float tf32r(float f) {
    return __uint_as_float(rna_tf32f(f));
}
__device__ __forceinline__ void mma_tf32(float& c0, float& c1, float& c2, float& c3,
                                         unsigned a0, unsigned a1, unsigned a2, unsigned a3,
                                         unsigned b0, unsigned b1) {
    asm volatile(
        "mma.sync.aligned.m16n8k8.row.col.f32.tf32.tf32.f32 "
        "{%0,%1,%2,%3}, {%4,%5,%6,%7}, {%8,%9}, {%0,%1,%2,%3};"
        : "+f"(c0), "+f"(c1), "+f"(c2), "+f"(c3)
        : "r"(a0), "r"(a1), "r"(a2), "r"(a3), "r"(b0), "r"(b1));
}

__device__ __forceinline__ void blockReduce2_128(float& a, float& b) {
    #pragma unroll
    for (int o = 16; o > 0; o >>= 1) {
        a += __shfl_xor_sync(0xffffffffu, a, o);
        b += __shfl_xor_sync(0xffffffffu, b, o);
    }
    __shared__ float sa[4], sb[4];
    int w = threadIdx.x >> 5;
    if ((threadIdx.x & 31) == 0) { sa[w] = a; sb[w] = b; }
    __syncthreads();
    a = sa[0] + sa[1] + sa[2] + sa[3];
    b = sb[0] + sb[1] + sb[2] + sb[3];
}

// ---------------- tf32 pre-round of all three weights (single launch) --------
__global__ void round3_tf32_kernel(const float* __restrict__ wa_in, float* __restrict__ wa_out,
                                   const float* __restrict__ w1_in, float* __restrict__ w1_out,
                                   const float* __restrict__ w2_in, float* __restrict__ w2_out) {
    const int n_a = D_*3*D_/4, n_1 = D_*2*DFF_/4, n_2 = DFF_*D_/4;
    int i = blockIdx.x * blockDim.x + threadIdx.x;
    const float4* src; float4* dst; int j;
    if (i < n_a)             { src = (const float4*)wa_in; dst = (float4*)wa_out; j = i; }
    else if (i < n_a + n_1)  { src = (const float4*)w1_in; dst = (float4*)w1_out; j = i - n_a; }
    else if (i < n_a + n_1 + n_2) { src = (const float4*)w2_in; dst = (float4*)w2_out; j = i - n_a - n_1; }
    else return;
    float4 v = src[j];
    v.x = tf32r(v.x); v.y = tf32r(v.y); v.z = tf32r(v.z); v.w = tf32r(v.w);
    dst[j] = v;
}

// ---------------- LayerNorm (output tf32-rounded: feeds GEMM A) ----------------
__global__ void ln_kernel(const float* __restrict__ x,
                          const float* __restrict__ g,
                          const float* __restrict__ bta,
                          float* __restrict__ out) {
    int row = blockIdx.x;
    int tid = threadIdx.x;
    const float4* xr = (const float4*)(x + (size_t)row * D_);
    float4 v = xr[tid];
    float s  = v.x + v.y + v.z + v.w;
    float sq = v.x*v.x + v.y*v.y + v.z*v.z + v.w*v.w;
    blockReduce2_128(s, sq);
    float mean = s * (1.0f / D_);
    float var  = sq * (1.0f / D_) - mean * mean;
    float inv  = rsqrtf(var + 1e-5f);
    float4 gg = ((const float4*)g)[tid];
    float4 bb = ((const float4*)bta)[tid];
    float4 o;
    o.x = tf32r((v.x - mean) * inv * gg.x + bb.x);
    o.y = tf32r((v.y - mean) * inv * gg.y + bb.y);
    o.z = tf32r((v.z - mean) * inv * gg.z + bb.z);
    o.w = tf32r((v.w - mean) * inv * gg.w + bb.w);
    ((float4*)(out + (size_t)row * D_))[tid] = o;
}

// ---------------- residual add + LayerNorm2 (h2 tf32-rounded; xres full) ------
__global__ void addres_ln2_kernel(const float* __restrict__ xv,
                                  const float* __restrict__ ao,
                                  const float* __restrict__ g,
                                  const float* __restrict__ bta,
                                  float* __restrict__ xres,
                                  float* __restrict__ h2) {
    int row = blockIdx.x;
    int b = row >> 10;
    int t = row & (T_ - 1);
    int tid = threadIdx.x;
    int d  = tid * 4;
    int h  = d >> 6;
    int dl = d & 63;
    float4 a = *(const float4*)(ao + ((((size_t)(b * H_ + h)) * T_ + t) * HD_ + dl));
    float4 v = ((const float4*)(xv + (size_t)row * D_))[tid];
    v.x += a.x; v.y += a.y; v.z += a.z; v.w += a.w;
    ((float4*)(xres + (size_t)row * D_))[tid] = v;
    float s  = v.x + v.y + v.z + v.w;
    float sq = v.x*v.x + v.y*v.y + v.z*v.z + v.w*v.w;
    blockReduce2_128(s, sq);
    float mean = s * (1.0f / D_);
    float var  = sq * (1.0f / D_) - mean * mean;
    float inv  = rsqrtf(var + 1e-5f);
    float4 gg = ((const float4*)g)[tid];
    float4 bb = ((const float4*)bta)[tid];
    float4 o;
    o.x = tf32r((v.x - mean) * inv * gg.x + bb.x);
    o.y = tf32r((v.y - mean) * inv * gg.y + bb.y);
    o.z = tf32r((v.z - mean) * inv * gg.z + bb.z);
    o.w = tf32r((v.w - mean) * inv * gg.w + bb.w);
    ((float4*)(h2 + (size_t)row * D_))[tid] = o;
}

// ========== tf32 GEMM (round-9 config: 128x128, warp 64x32, 2-stage) =========
// EPI 0: plain (+bias/+res).  EPI 2: SwiGLU epilogue (B cols remapped).
#define ASTRIDE 36
#define BSTRIDE 136
#define STAGE_WORDS (128*ASTRIDE + 32*BSTRIDE)   // 8960
#define GSMEM_BYTES (2 * STAGE_WORDS * 4)        // 71680

template<int EPI, bool HAS_BIAS, bool HAS_RES>
__global__ __launch_bounds__(256, 2)
void tf32_gemm(const float* __restrict__ A, const float* __restrict__ Bm,
               const float* __restrict__ bias, const float* __restrict__ res,
               float* __restrict__ C, int M, int N, int K) {
    extern __shared__ float smem[];
    const unsigned sbase = (unsigned)__cvta_generic_to_shared(smem);
    const int t = threadIdx.x;
    const int bx = blockIdx.x;
    const int m0 = blockIdx.y * 128;
    const int n0 = bx * 128;
    const int warp = t >> 5, lane = t & 31;
    const int wm = (warp >> 2) * 64;
    const int wn32 = (warp & 3) * 32;
    const int wn16 = (warp & 3) * 16;
    const int g  = lane >> 2, tig = lane & 3;

    float acc[4][4][4];
    #pragma unroll
    for (int i = 0; i < 4; i++)
        #pragma unroll
        for (int j = 0; j < 4; j++)
            #pragma unroll
            for (int e = 0; e < 4; e++) acc[i][j][e] = 0.f;

    const int mA = t >> 3, k4 = t & 7;
    const int kB = t >> 5, n4 = t & 31;
    int bcol;
    if (EPI == 2) bcol = (n4 < 16) ? bx*64 + n4*4 : DFF_ + bx*64 + (n4-16)*4;
    else          bcol = n0 + n4*4;

    int bfcol[4];
    #pragma unroll
    for (int nt = 0; nt < 4; nt++)
        bfcol[nt] = (EPI == 2) ? ((nt < 2) ? wn16 + nt*8 : 64 + wn16 + (nt-2)*8)
                               : wn32 + nt*8;

    {
        unsigned sA = sbase;
        unsigned sB = sbase + 128*ASTRIDE*4;
        #pragma unroll
        for (int j = 0; j < 4; j++) {
            int ma = mA + 32*j;
            cpasync16(sA + (ma*ASTRIDE + k4*4)*4, A + (size_t)(m0 + ma)*K + k4*4);
            int kb = kB + 8*j;
            cpasync16(sB + (kb*BSTRIDE + n4*4)*4, Bm + (size_t)kb*N + bcol);
        }
        cpcommit();
    }

    const int nIter = K >> 5;
    int buf = 0;
    for (int it = 0; it < nIter; ++it) {
        if (it + 1 < nIter) {
            int k0 = (it + 1) << 5;
            unsigned sA = sbase + (buf ^ 1) * STAGE_WORDS * 4;
            unsigned sB = sA + 128*ASTRIDE*4;
            #pragma unroll
            for (int j = 0; j < 4; j++) {
                int ma = mA + 32*j;
                cpasync16(sA + (ma*ASTRIDE + k4*4)*4,
                          A + (size_t)(m0 + ma)*K + k0 + k4*4);
                int kb = kB + 8*j;
                cpasync16(sB + (kb*BSTRIDE + n4*4)*4,
                          Bm + (size_t)(k0 + kb)*N + bcol);
            }
            cpcommit();
            asm volatile("cp.async.wait_group 1;");
        } else {
            asm volatile("cp.async.wait_group 0;");
        }
        __syncthreads();

        const unsigned* Asu = (const unsigned*)(smem + buf * STAGE_WORDS);
        const unsigned* Bsu = Asu + 128*ASTRIDE;

        #pragma unroll
        for (int ks = 0; ks < 4; ks++) {
            unsigned a[4][4], b[4][2];
            #pragma unroll
            for (int mt = 0; mt < 4; mt++) {
                const unsigned* p = Asu + (wm + mt*16 + g)*ASTRIDE + ks*8 + tig;
                a[mt][0] = p[0];
                a[mt][1] = p[8*ASTRIDE];
                a[mt][2] = p[4];
                a[mt][3] = p[8*ASTRIDE + 4];
            }
            #pragma unroll
            for (int nt = 0; nt < 4; nt++) {
                const unsigned* p = Bsu + (ks*8 + tig)*BSTRIDE + bfcol[nt] + g;
                b[nt][0] = p[0];
                b[nt][1] = p[4*BSTRIDE];
            }
            #pragma unroll
            for (int mt = 0; mt < 4; mt++)
                #pragma unroll
                for (int nt = 0; nt < 4; nt++)
                    mma_tf32(acc[mt][nt][0], acc[mt][nt][1],
                             acc[mt][nt][2], acc[mt][nt][3],
                             a[mt][0], a[mt][1], a[mt][2], a[mt][3],
                             b[nt][0], b[nt][1]);
        }
        __syncthreads();
        buf ^= 1;
    }

    // ================== epilogues ==================
    if (EPI == 0) {
        #pragma unroll
        for (int mt = 0; mt < 4; mt++) {
            int row0 = m0 + wm + mt * 16 + g;
            #pragma unroll
            for (int nt = 0; nt < 4; nt++) {
                int col = n0 + wn32 + nt * 8 + tig * 2;
                float2 v0 = make_float2(acc[mt][nt][0], acc[mt][nt][1]);
                float2 v1 = make_float2(acc[mt][nt][2], acc[mt][nt][3]);
                if (HAS_BIAS) {
                    float2 bb = *(const float2*)(bias + col);
                    v0.x += bb.x; v0.y += bb.y; v1.x += bb.x; v1.y += bb.y;
                }
                if (HAS_RES) {
                    float2 r0 = *(const float2*)(res + (size_t)row0 * N + col);
                    float2 r1 = *(const float2*)(res + (size_t)(row0 + 8) * N + col);
                    v0.x += r0.x; v0.y += r0.y; v1.x += r1.x; v1.y += r1.y;
                }
                *(float2*)(C + (size_t)row0 * N + col) = v0;
                *(float2*)(C + (size_t)(row0 + 8) * N + col) = v1;
            }
        }
    } else {  // EPI == 2: g = (a + ba) * silu(gate + bg), tf32-rounded store
        #pragma unroll
        for (int mt = 0; mt < 4; mt++) {
            int row0 = m0 + wm + mt * 16 + g;
            #pragma unroll
            for (int nt = 0; nt < 2; nt++) {
                int col = bx*64 + wn16 + nt*8 + 2*tig;
                float2 ba = *(const float2*)(bias + col);
                float2 bg = *(const float2*)(bias + DFF_ + col);
                float a00 = acc[mt][nt][0] + ba.x, a01 = acc[mt][nt][1] + ba.y;
                float a10 = acc[mt][nt][2] + ba.x, a11 = acc[mt][nt][3] + ba.y;
                float g00 = acc[mt][nt+2][0] + bg.x, g01 = acc[mt][nt+2][1] + bg.y;
                float g10 = acc[mt][nt+2][2] + bg.x, g11 = acc[mt][nt+2][3] + bg.y;
                float2 o0 = make_float2(tf32r(a00 * (g00 / (1.f + __expf(-g00)))),
                                        tf32r(a01 * (g01 / (1.f + __expf(-g01)))));
                float2 o1 = make_float2(tf32r(a10 * (g10 / (1.f + __expf(-g10)))),
                                        tf32r(a11 * (g11 / (1.f + __expf(-g11)))));
                *(float2*)(C + (size_t)row0 * DFF_ + col) = o0;
                *(float2*)(C + (size_t)(row0 + 8) * DFF_ + col) = o1;
            }
        }
    }
}

// ---------------- QKV epilogue (Q/K/V tf32-rounded; fast __sincosf) ----------
// __sincosf error (~1e-5..1e-4 abs) is below the tf32 quantum applied right
// after, so the perturbation is mostly absorbed by the rounding.
__global__ void qkv_post_kernel(const float* __restrict__ qkv,
                                const int*   __restrict__ x_type,
                                const float* __restrict__ type_emb,
                                const float* __restrict__ seq_order,
                                float* __restrict__ Q, float* __restrict__ Ko,
                                float* __restrict__ V) {
    int row = blockIdx.x;       // b*T + t
    int b = row >> 10;
    int t = row & (T_ - 1);
    int p = threadIdx.x;        // 0..255 -> dim pair (2p, 2p+1)
    int d2 = 2 * p;

    int tq = x_type[b * (T_ + 1) + t];
    int tk = x_type[b * (T_ + 1) + t + 1];
    float pq = seq_order[b * (T_ + 1) + t];
    float pk = seq_order[b * (T_ + 1) + t + 1];

    const float* qr = qkv + (size_t)row * (3 * D_);
    float q0 = qr[d2]           + type_emb[(size_t)tq * (2 * D_) + d2];
    float q1 = qr[d2 + 1]       + type_emb[(size_t)tq * (2 * D_) + d2 + 1];
    float k0 = qr[D_ + d2]      + type_emb[(size_t)tk * (2 * D_) + D_ + d2];
    float k1 = qr[D_ + d2 + 1]  + type_emb[(size_t)tk * (2 * D_) + D_ + d2 + 1];
    float v0 = qr[2 * D_ + d2];
    float v1 = qr[2 * D_ + d2 + 1];

    int h  = d2 >> 6;
    int dl = d2 & 63;
    if (dl < DPR_) {
        float f = exp2f((float)dl * (-13.287712379549449f / 32.0f));
        float sq_, cq_, sk_, ck_;
        __sincosf(pq * f, &sq_, &cq_);
        __sincosf(pk * f, &sk_, &ck_);
        float nq0 = q0 * cq_ - q1 * sq_;
        float nq1 = q1 * cq_ + q0 * sq_;
        float nk0 = k0 * ck_ - k1 * sk_;
        float nk1 = k1 * ck_ + k0 * sk_;
        q0 = nq0; q1 = nq1; k0 = nk0; k1 = nk1;
    }
    size_t o = (((size_t)(b * H_ + h)) * T_ + t) * HD_ + dl;
    Q[o] = tf32r(q0); Q[o + 1] = tf32r(q1);
    Ko[o] = tf32r(k0); Ko[o + 1] = tf32r(k1);
    V[o] = tf32r(v0); V[o + 1] = tf32r(v1);
}

// ====== tf32 flash attention: 512 CTAs, big-first schedule, 2-stage ==========
#define AT_PAD 68
#define AT_STAGE (2*64*AT_PAD)
#define AT_SMEM (2*AT_STAGE*4)

__global__ __launch_bounds__(256, 2)
void attn_tc_kernel(const float* __restrict__ Q, const float* __restrict__ Kc,
                    const float* __restrict__ V, float* __restrict__ O) {
    extern __shared__ float sm[];
    const unsigned sbase = (unsigned)__cvta_generic_to_shared(sm);
    const int qt = 7 - blockIdx.x;    // big q-tiles scheduled first
    const int h  = blockIdx.y;
    const int b  = blockIdx.z;
    const int t = threadIdx.x;
    const int warp = t >> 5, lane = t & 31;
    const int g = lane >> 2, tig = lane & 3;
    const int wm = warp * 16;
    const size_t hb = ((size_t)(b * H_ + h)) * T_ * HD_;

    const int cr = t >> 4;
    const int cc4 = (t & 15) * 4;
    const int qbase = qt * 128;

    // Q pre-rounded; *0.125 is exact in tf32 -> no cvt needed
    unsigned qa[8][4];
    {
        const float* Qp = Q + hb + (size_t)(qbase + wm) * HD_;
        #pragma unroll
        for (int ks = 0; ks < 8; ks++) {
            int c0 = ks * 8 + tig;
            qa[ks][0] = __float_as_uint(Qp[g * 64 + c0] * 0.125f);
            qa[ks][1] = __float_as_uint(Qp[(g + 8) * 64 + c0] * 0.125f);
            qa[ks][2] = __float_as_uint(Qp[g * 64 + c0 + 4] * 0.125f);
            qa[ks][3] = __float_as_uint(Qp[(g + 8) * 64 + c0 + 4] * 0.125f);
        }
    }

    float m0 = -1e30f, m1 = -1e30f, l0 = 0.f, l1 = 0.f;
    float o[8][4];
    #pragma unroll
    for (int nt = 0; nt < 8; nt++)
        #pragma unroll
        for (int e = 0; e < 4; e++) o[nt][e] = 0.f;

    const int nT = qt * 2 + 2;

    {
        unsigned sK = sbase;
        unsigned sV = sK + 64 * AT_PAD * 4;
        const float* kp = Kc + hb;
        const float* vp = V + hb;
        #pragma unroll
        for (int j = 0; j < 4; j++) {
            int r = cr + 16 * j;
            cpasync16(sK + (r * AT_PAD + cc4) * 4, kp + r * 64 + cc4);
            cpasync16(sV + (r * AT_PAD + cc4) * 4, vp + r * 64 + cc4);
        }
        cpcommit();
    }

    int buf = 0;
    for (int kt = 0; kt < nT; kt++) {
        const int j0 = kt * 64;
        if (kt + 1 < nT) {
            unsigned sK = sbase + (buf ^ 1) * AT_STAGE * 4;
            unsigned sV = sK + 64 * AT_PAD * 4;
            const float* kp = Kc + hb + (size_t)(j0 + 64) * 64;
            const float* vp = V + hb + (size_t)(j0 + 64) * 64;
            #pragma unroll
            for (int j = 0; j < 4; j++) {
                int r = cr + 16 * j;
                cpasync16(sK + (r * AT_PAD + cc4) * 4, kp + r * 64 + cc4);
                cpasync16(sV + (r * AT_PAD + cc4) * 4, vp + r * 64 + cc4);
            }
            cpcommit();
            asm volatile("cp.async.wait_group 1;");
        } else {
            asm volatile("cp.async.wait_group 0;");
        }
        __syncthreads();

        if (j0 <= qbase + wm + 15) {
            const unsigned* Ksmu = (const unsigned*)(sm + buf * AT_STAGE);
            const unsigned* Vsmu = Ksmu + 64 * AT_PAD;

            float s[8][4];
            #pragma unroll
            for (int nt = 0; nt < 8; nt++) {
                float c0 = 0.f, c1 = 0.f, c2 = 0.f, c3 = 0.f;
                const unsigned* kp = Ksmu + (nt * 8 + g) * AT_PAD + tig;
                #pragma unroll
                for (int ks = 0; ks < 8; ks++) {
                    mma_tf32(c0, c1, c2, c3,
                             qa[ks][0], qa[ks][1], qa[ks][2], qa[ks][3],
                             kp[ks * 8], kp[ks * 8 + 4]);
                }
                s[nt][0] = c0; s[nt][1] = c1; s[nt][2] = c2; s[nt][3] = c3;
            }

            const int r0 = qbase + wm + g, r1 = r0 + 8;
            if (j0 + 63 > qbase + wm) {
                #pragma unroll
                for (int nt = 0; nt < 8; nt++) {
                    int col = j0 + nt * 8 + 2 * tig;
                    if (col > r0)     s[nt][0] = -1e30f;
                    if (col + 1 > r0) s[nt][1] = -1e30f;
                    if (col > r1)     s[nt][2] = -1e30f;
                    if (col + 1 > r1) s[nt][3] = -1e30f;
                }
            }

            float mx0 = -1e30f, mx1 = -1e30f;
            #pragma unroll
            for (int nt = 0; nt < 8; nt++) {
                mx0 = fmaxf(mx0, fmaxf(s[nt][0], s[nt][1]));
                mx1 = fmaxf(mx1, fmaxf(s[nt][2], s[nt][3]));
            }
            mx0 = fmaxf(mx0, __shfl_xor_sync(0xffffffffu, mx0, 1));
            mx0 = fmaxf(mx0, __shfl_xor_sync(0xffffffffu, mx0, 2));
            mx1 = fmaxf(mx1, __shfl_xor_sync(0xffffffffu, mx1, 1));
            mx1 = fmaxf(mx1, __shfl_xor_sync(0xffffffffu, mx1, 2));
            float nm0 = fmaxf(m0, mx0), nm1 = fmaxf(m1, mx1);
            float sc0 = __expf(m0 - nm0), sc1 = __expf(m1 - nm1);
            m0 = nm0; m1 = nm1;
            float sum0 = 0.f, sum1 = 0.f;
            #pragma unroll
            for (int nt = 0; nt < 8; nt++) {
                s[nt][0] = __expf(s[nt][0] - m0); sum0 += s[nt][0];
                s[nt][1] = __expf(s[nt][1] - m0); sum0 += s[nt][1];
                s[nt][2] = __expf(s[nt][2] - m1); sum1 += s[nt][2];
                s[nt][3] = __expf(s[nt][3] - m1); sum1 += s[nt][3];
            }
            l0 = l0 * sc0 + sum0;
            l1 = l1 * sc1 + sum1;
            #pragma unroll
            for (int nt = 0; nt < 8; nt++) {
                o[nt][0] *= sc0; o[nt][1] *= sc0;
                o[nt][2] *= sc1; o[nt][3] *= sc1;
            }

            #pragma unroll
            for (int ks = 0; ks < 8; ks++) {
                const int srcA = (lane & 0x1c) | (tig >> 1);
                float v00 = __shfl_sync(0xffffffffu, s[ks][0], srcA);
                float v01 = __shfl_sync(0xffffffffu, s[ks][1], srcA);
                float a0f = (tig & 1) ? v01 : v00;
                float v02 = __shfl_sync(0xffffffffu, s[ks][0], srcA + 2);
                float v03 = __shfl_sync(0xffffffffu, s[ks][1], srcA + 2);
                float a2f = (tig & 1) ? v03 : v02;
                float w00 = __shfl_sync(0xffffffffu, s[ks][2], srcA);
                float w01 = __shfl_sync(0xffffffffu, s[ks][3], srcA);
                float a1f = (tig & 1) ? w01 : w00;
                float w02 = __shfl_sync(0xffffffffu, s[ks][2], srcA + 2);
                float w03 = __shfl_sync(0xffffffffu, s[ks][3], srcA + 2);
                float a3f = (tig & 1) ? w03 : w02;
                unsigned a0 = rna_tf32f(a0f), a1 = rna_tf32f(a1f);
                unsigned a2 = rna_tf32f(a2f), a3 = rna_tf32f(a3f);
                const unsigned* vp = Vsmu + (ks * 8 + tig) * AT_PAD + g;
                #pragma unroll
                for (int nt = 0; nt < 8; nt++) {
                    mma_tf32(o[nt][0], o[nt][1], o[nt][2], o[nt][3],
                             a0, a1, a2, a3,
                             vp[nt * 8], vp[4 * AT_PAD + nt * 8]);
                }
            }
        }
        __syncthreads();
        buf ^= 1;
    }

    l0 += __shfl_xor_sync(0xffffffffu, l0, 1);
    l0 += __shfl_xor_sync(0xffffffffu, l0, 2);
    l1 += __shfl_xor_sync(0xffffffffu, l1, 1);
    l1 += __shfl_xor_sync(0xffffffffu, l1, 2);
    float inv0 = 1.0f / l0, inv1 = 1.0f / l1;
    float* Op = O + hb + (size_t)(qbase + wm) * HD_;
    #pragma unroll
    for (int nt = 0; nt < 8; nt++) {
        int col = nt * 8 + 2 * tig;
        *(float2*)(Op + g * 64 + col) =
            make_float2(o[nt][0] * inv0, o[nt][1] * inv0);
        *(float2*)(Op + (g + 8) * 64 + col) =
            make_float2(o[nt][2] * inv1, o[nt][3] * inv1);
    }
}

// ---------------- launch ----------------
extern "C" void kernel_launch(void* const* d_in, const int* in_sizes, int n_in,
                              void* d_out, int out_size) {
    (void)in_sizes; (void)n_in; (void)out_size;
    const int*   x_type   = (const int*)  d_in[0];
    const float* x_value  = (const float*)d_in[1];
    const float* seq_ord  = (const float*)d_in[2];
    const float* W_attn   = (const float*)d_in[3];
    const float* type_emb = (const float*)d_in[4];
    const float* ln1_g    = (const float*)d_in[5];
    const float* ln1_b    = (const float*)d_in[6];
    const float* ln2_g    = (const float*)d_in[7];
    const float* ln2_b    = (const float*)d_in[8];
    const float* W1       = (const float*)d_in[9];
    const float* b1       = (const float*)d_in[10];
    const float* W2       = (const float*)d_in[11];
    const float* b2       = (const float*)d_in[12];
    float* out = (float*)d_out;

    float *p_h, *p_qkv, *p_q, *p_k, *p_v, *p_ao, *p_xres, *p_h2, *p_g;
    float *p_wa, *p_w1, *p_w2;
    cudaGetSymbolAddress((void**)&p_h,    g_h);
    cudaGetSymbolAddress((void**)&p_qkv,  g_qkv);
    cudaGetSymbolAddress((void**)&p_q,    g_q);
    cudaGetSymbolAddress((void**)&p_k,    g_k);
    cudaGetSymbolAddress((void**)&p_v,    g_v);
    cudaGetSymbolAddress((void**)&p_ao,   g_ao);
    cudaGetSymbolAddress((void**)&p_xres, g_xres);
    cudaGetSymbolAddress((void**)&p_h2,   g_h2);
    cudaGetSymbolAddress((void**)&p_g,    g_g);
    cudaGetSymbolAddress((void**)&p_wa,   g_wa);
    cudaGetSymbolAddress((void**)&p_w1,   g_w1);
    cudaGetSymbolAddress((void**)&p_w2,   g_w2);

    cudaFuncSetAttribute(tf32_gemm<0, false, false>,
                         cudaFuncAttributeMaxDynamicSharedMemorySize, GSMEM_BYTES);
    cudaFuncSetAttribute(tf32_gemm<2, true, false>,
                         cudaFuncAttributeMaxDynamicSharedMemorySize, GSMEM_BYTES);
    cudaFuncSetAttribute(tf32_gemm<0, true, true>,
                         cudaFuncAttributeMaxDynamicSharedMemorySize, GSMEM_BYTES);
    cudaFuncSetAttribute(attn_tc_kernel,
                         cudaFuncAttributeMaxDynamicSharedMemorySize, AT_SMEM);

    // 0. pre-round all weights to tf32 in ONE launch
    {
        const int n4 = D_*3*D_/4 + D_*2*DFF_/4 + DFF_*D_/4;
        round3_tf32_kernel<<<(n4 + 255)/256, 256>>>(W_attn, p_wa, W1, p_w1, W2, p_w2);
    }
    // 1. LN1 (tf32-rounded output)
    ln_kernel<<<ROWS_, 128>>>(x_value, ln1_g, ln1_b, p_h);
    // 2. QKV GEMM: [8192,512] @ [512,1536]
    tf32_gemm<0, false, false><<<dim3(12, ROWS_ / 128), 256, GSMEM_BYTES>>>(
        p_h, p_wa, nullptr, nullptr, p_qkv, ROWS_, 3 * D_, D_);
    // 3. emb + RoPE + transpose (tf32-rounded Q/K/V)
    qkv_post_kernel<<<ROWS_, 256>>>(p_qkv, x_type, type_emb, seq_ord, p_q, p_k, p_v);
    // 4. causal flash attention (512 CTAs, big q-tiles first)
    attn_tc_kernel<<<dim3(8, H_, B_), 256, AT_SMEM>>>(p_q, p_k, p_v, p_ao);
    // 5. residual + LN2
    addres_ln2_kernel<<<ROWS_, 128>>>(x_value, p_ao, ln2_g, ln2_b, p_xres, p_h2);
    // 6. FFN GEMM1 + fused bias + SwiGLU epilogue -> g (tf32-rounded)
    tf32_gemm<2, true, false><<<dim3(16, ROWS_ / 128), 256, GSMEM_BYTES>>>(
        p_h2, p_w1, b1, nullptr, p_g, ROWS_, 2 * DFF_, D_);
    // 7. FFN GEMM2 + bias + residual -> out
    tf32_gemm<0, true, true><<<dim3(4, ROWS_ / 128), 256, GSMEM_BYTES>>>(
        p_g, p_w2, b2, p_xres, out, ROWS_, D_, DFF_);
}

// round 14
// speedup vs baseline: 1.0705x; 1.0705x over previous
#include <cuda_runtime.h>
#include <cuda_bf16.h>
#include <math.h>

// Problem constants
#define B_  8
#define T_  1024
#define D_  512
#define H_  8
#define HD_ 64
#define DFF_ 1024
#define DPR_ 32
#define ROWS_ (B_*T_)   // 8192

// ---------------- scratch (device globals; no allocation allowed) ----------------
__device__ float g_h   [ROWS_*D_];        // ln1 output (tf32-rounded)
__device__ float g_qkv [ROWS_*3*D_];      // qkv projection (full fp32)
__device__ float g_q   [B_*H_*T_*HD_];    // [B,H,T,HD] (tf32-rounded)
__device__ float g_k   [B_*H_*T_*HD_];    // (tf32-rounded)
__device__ float g_v   [B_*H_*T_*HD_];    // (tf32-rounded)
__device__ float g_ao  [B_*H_*T_*HD_];    // attention out (full fp32)
__device__ float g_xres[ROWS_*D_];        // x_value + attn (full fp32)
__device__ float g_h2  [ROWS_*D_];        // ln2 output (tf32-rounded)
__device__ float g_g   [ROWS_*DFF_];      // swiglu output (tf32-rounded)
__device__ float g_wa  [D_*3*D_];         // W_attn tf32-rounded
__device__ float g_w1  [D_*2*DFF_];       // W1 tf32-rounded
__device__ float g_w2  [DFF_*D_];         // W2 tf32-rounded

// ---------------- helpers ----------------
__device__ __forceinline__ void cpasync16(unsigned s, const void* g) {
    asm volatile("cp.async.cg.shared.global [%0], [%1], 16;" :: "r"(s), "l"(g));
}
__device__ __forceinline__ void cpcommit() {
    asm volatile("cp.async.commit_group;");
}
__device__ __forceinline__ unsigned rna_tf32f(float f) {
    unsigned r;
    asm("cvt.rna.tf32.f32 %0, %1;" : "=r"(r) : "f"(f));
    return r;
}
__device__ __forceinline__ float tf32r(float f) {
    return __uint_as_float(rna_tf32f(f));
}
__device__ __forceinline__ void mma_tf32(float& c0, float& c1, float& c2, float& c3,
                                         unsigned a0, unsigned a1, unsigned a2, unsigned a3,
                                         unsigned b0, unsigned b1) {
    asm volatile(
        "mma.sync.aligned.m16n8k8.row.col.f32.tf32.tf32.f32 "
        "{%0,%1,%2,%3}, {%4,%5,%6,%7}, {%8,%9}, {%0,%1,%2,%3};"
        : "+f"(c0), "+f"(c1), "+f"(c2), "+f"(c3)
        : "r"(a0), "r"(a1), "r"(a2), "r"(a3), "r"(b0), "r"(b1));
}

__device__ __forceinline__ void blockReduce2_128(float& a, float& b) {
    #pragma unroll
    for (int o = 16; o > 0; o >>= 1) {
        a += __shfl_xor_sync(0xffffffffu, a, o);
        b += __shfl_xor_sync(0xffffffffu, b, o);
    }
    __shared__ float sa[4], sb[4];
    int w = threadIdx.x >> 5;
    if ((threadIdx.x & 31) == 0) { sa[w] = a; sb[w] = b; }
    __syncthreads();
    a = sa[0] + sa[1] + sa[2] + sa[3];
    b = sb[0] + sb[1] + sb[2] + sb[3];
}

// ---------------- tf32 pre-round of all three weights (single launch) --------
__global__ void round3_tf32_kernel(const float* __restrict__ wa_in, float* __restrict__ wa_out,
                                   const float* __restrict__ w1_in, float* __restrict__ w1_out,
                                   const float* __restrict__ w2_in, float* __restrict__ w2_out) {
    const int n_a = D_*3*D_/4, n_1 = D_*2*DFF_/4, n_2 = DFF_*D_/4;
    int i = blockIdx.x * blockDim.x + threadIdx.x;
    const float4* src; float4* dst; int j;
    if (i < n_a)             { src = (const float4*)wa_in; dst = (float4*)wa_out; j = i; }
    else if (i < n_a + n_1)  { src = (const float4*)w1_in; dst = (float4*)w1_out; j = i - n_a; }
    else if (i < n_a + n_1 + n_2) { src = (const float4*)w2_in; dst = (float4*)w2_out; j = i - n_a - n_1; }
    else return;
    float4 v = src[j];
    v.x = tf32r(v.x); v.y = tf32r(v.y); v.z = tf32r(v.z); v.w = tf32r(v.w);
    dst[j] = v;
}

// ---------------- LayerNorm (output tf32-rounded: feeds GEMM A) ----------------
__global__ void ln_kernel(const float* __restrict__ x,
                          const float* __restrict__ g,
                          const float* __restrict__ bta,
                          float* __restrict__ out) {
    int row = blockIdx.x;
    int tid = threadIdx.x;
    const float4* xr = (const float4*)(x + (size_t)row * D_);
    float4 v = xr[tid];
    float s  = v.x + v.y + v.z + v.w;
    float sq = v.x*v.x + v.y*v.y + v.z*v.z + v.w*v.w;
    blockReduce2_128(s, sq);
    float mean = s * (1.0f / D_);
    float var  = sq * (1.0f / D_) - mean * mean;
    float inv  = rsqrtf(var + 1e-5f);
    float4 gg = ((const float4*)g)[tid];
    float4 bb = ((const float4*)bta)[tid];
    float4 o;
    o.x = tf32r((v.x - mean) * inv * gg.x + bb.x);
    o.y = tf32r((v.y - mean) * inv * gg.y + bb.y);
    o.z = tf32r((v.z - mean) * inv * gg.z + bb.z);
    o.w = tf32r((v.w - mean) * inv * gg.w + bb.w);
    ((float4*)(out + (size_t)row * D_))[tid] = o;
}

// ---------------- residual add + LayerNorm2 (h2 tf32-rounded; xres full) ------
__global__ void addres_ln2_kernel(const float* __restrict__ xv,
                                  const float* __restrict__ ao,
                                  const float* __restrict__ g,
                                  const float* __restrict__ bta,
                                  float* __restrict__ xres,
                                  float* __restrict__ h2) {
    int row = blockIdx.x;
    int b = row >> 10;
    int t = row & (T_ - 1);
    int tid = threadIdx.x;
    int d  = tid * 4;
    int h  = d >> 6;
    int dl = d & 63;
    float4 a = *(const float4*)(ao + ((((size_t)(b * H_ + h)) * T_ + t) * HD_ + dl));
    float4 v = ((const float4*)(xv + (size_t)row * D_))[tid];
    v.x += a.x; v.y += a.y; v.z += a.z; v.w += a.w;
    ((float4*)(xres + (size_t)row * D_))[tid] = v;
    float s  = v.x + v.y + v.z + v.w;
    float sq = v.x*v.x + v.y*v.y + v.z*v.z + v.w*v.w;
    blockReduce2_128(s, sq);
    float mean = s * (1.0f / D_);
    float var  = sq * (1.0f / D_) - mean * mean;
    float inv  = rsqrtf(var + 1e-5f);
    float4 gg = ((const float4*)g)[tid];
    float4 bb = ((const float4*)bta)[tid];
    float4 o;
    o.x = tf32r((v.x - mean) * inv * gg.x + bb.x);
    o.y = tf32r((v.y - mean) * inv * gg.y + bb.y);
    o.z = tf32r((v.z - mean) * inv * gg.z + bb.z);
    o.w = tf32r((v.w - mean) * inv * gg.w + bb.w);
    ((float4*)(h2 + (size_t)row * D_))[tid] = o;
}

// ========== tf32 GEMM (round-9 config: 128x128, warp 64x32, 2-stage) =========
// EPI 0: plain (+bias/+res).  EPI 2: SwiGLU epilogue (B cols remapped).
#define ASTRIDE 36
#define BSTRIDE 136
#define STAGE_WORDS (128*ASTRIDE + 32*BSTRIDE)   // 8960
#define GSMEM_BYTES (2 * STAGE_WORDS * 4)        // 71680

template<int EPI, bool HAS_BIAS, bool HAS_RES>
__global__ __launch_bounds__(256, 2)
void tf32_gemm(const float* __restrict__ A, const float* __restrict__ Bm,
               const float* __restrict__ bias, const float* __restrict__ res,
               float* __restrict__ C, int M, int N, int K) {
    extern __shared__ float smem[];
    const unsigned sbase = (unsigned)__cvta_generic_to_shared(smem);
    const int t = threadIdx.x;
    const int bx = blockIdx.x;
    const int m0 = blockIdx.y * 128;
    const int n0 = bx * 128;
    const int warp = t >> 5, lane = t & 31;
    const int wm = (warp >> 2) * 64;
    const int wn32 = (warp & 3) * 32;
    const int wn16 = (warp & 3) * 16;
    const int g  = lane >> 2, tig = lane & 3;

    float acc[4][4][4];
    #pragma unroll
    for (int i = 0; i < 4; i++)
        #pragma unroll
        for (int j = 0; j < 4; j++)
            #pragma unroll
            for (int e = 0; e < 4; e++) acc[i][j][e] = 0.f;

    const int mA = t >> 3, k4 = t & 7;
    const int kB = t >> 5, n4 = t & 31;
    int bcol;
    if (EPI == 2) bcol = (n4 < 16) ? bx*64 + n4*4 : DFF_ + bx*64 + (n4-16)*4;
    else          bcol = n0 + n4*4;

    int bfcol[4];
    #pragma unroll
    for (int nt = 0; nt < 4; nt++)
        bfcol[nt] = (EPI == 2) ? ((nt < 2) ? wn16 + nt*8 : 64 + wn16 + (nt-2)*8)
                               : wn32 + nt*8;

    {
        unsigned sA = sbase;
        unsigned sB = sbase + 128*ASTRIDE*4;
        #pragma unroll
        for (int j = 0; j < 4; j++) {
            int ma = mA + 32*j;
            cpasync16(sA + (ma*ASTRIDE + k4*4)*4, A + (size_t)(m0 + ma)*K + k4*4);
            int kb = kB + 8*j;
            cpasync16(sB + (kb*BSTRIDE + n4*4)*4, Bm + (size_t)kb*N + bcol);
        }
        cpcommit();
    }

    const int nIter = K >> 5;
    int buf = 0;
    for (int it = 0; it < nIter; ++it) {
        if (it + 1 < nIter) {
            int k0 = (it + 1) << 5;
            unsigned sA = sbase + (buf ^ 1) * STAGE_WORDS * 4;
            unsigned sB = sA + 128*ASTRIDE*4;
            #pragma unroll
            for (int j = 0; j < 4; j++) {
                int ma = mA + 32*j;
                cpasync16(sA + (ma*ASTRIDE + k4*4)*4,
                          A + (size_t)(m0 + ma)*K + k0 + k4*4);
                int kb = kB + 8*j;
                cpasync16(sB + (kb*BSTRIDE + n4*4)*4,
                          Bm + (size_t)(k0 + kb)*N + bcol);
            }
            cpcommit();
            asm volatile("cp.async.wait_group 1;");
        } else {
            asm volatile("cp.async.wait_group 0;");
        }
        __syncthreads();

        const unsigned* Asu = (const unsigned*)(smem + buf * STAGE_WORDS);
        const unsigned* Bsu = Asu + 128*ASTRIDE;

        #pragma unroll
        for (int ks = 0; ks < 4; ks++) {
            unsigned a[4][4], b[4][2];
            #pragma unroll
            for (int mt = 0; mt < 4; mt++) {
                const unsigned* p = Asu + (wm + mt*16 + g)*ASTRIDE + ks*8 + tig;
                a[mt][0] = p[0];
                a[mt][1] = p[8*ASTRIDE];
                a[mt][2] = p[4];
                a[mt][3] = p[8*ASTRIDE + 4];
            }
            #pragma unroll
            for (int nt = 0; nt < 4; nt++) {
                const unsigned* p = Bsu + (ks*8 + tig)*BSTRIDE + bfcol[nt] + g;
                b[nt][0] = p[0];
                b[nt][1] = p[4*BSTRIDE];
            }
            #pragma unroll
            for (int mt = 0; mt < 4; mt++)
                #pragma unroll
                for (int nt = 0; nt < 4; nt++)
                    mma_tf32(acc[mt][nt][0], acc[mt][nt][1],
                             acc[mt][nt][2], acc[mt][nt][3],
                             a[mt][0], a[mt][1], a[mt][2], a[mt][3],
                             b[nt][0], b[nt][1]);
        }
        __syncthreads();
        buf ^= 1;
    }

    // ================== epilogues ==================
    if (EPI == 0) {
        #pragma unroll
        for (int mt = 0; mt < 4; mt++) {
            int row0 = m0 + wm + mt * 16 + g;
            #pragma unroll
            for (int nt = 0; nt < 4; nt++) {
                int col = n0 + wn32 + nt * 8 + tig * 2;
                float2 v0 = make_float2(acc[mt][nt][0], acc[mt][nt][1]);
                float2 v1 = make_float2(acc[mt][nt][2], acc[mt][nt][3]);
                if (HAS_BIAS) {
                    float2 bb = *(const float2*)(bias + col);
                    v0.x += bb.x; v0.y += bb.y; v1.x += bb.x; v1.y += bb.y;
                }
                if (HAS_RES) {
                    float2 r0 = *(const float2*)(res + (size_t)row0 * N + col);
                    float2 r1 = *(const float2*)(res + (size_t)(row0 + 8) * N + col);
                    v0.x += r0.x; v0.y += r0.y; v1.x += r1.x; v1.y += r1.y;
                }
                *(float2*)(C + (size_t)row0 * N + col) = v0;
                *(float2*)(C + (size_t)(row0 + 8) * N + col) = v1;
            }
        }
    } else {  // EPI == 2: g = (a + ba) * silu(gate + bg), tf32-rounded store
        #pragma unroll
        for (int mt = 0; mt < 4; mt++) {
            int row0 = m0 + wm + mt * 16 + g;
            #pragma unroll
            for (int nt = 0; nt < 2; nt++) {
                int col = bx*64 + wn16 + nt*8 + 2*tig;
                float2 ba = *(const float2*)(bias + col);
                float2 bg = *(const float2*)(bias + DFF_ + col);
                float a00 = acc[mt][nt][0] + ba.x, a01 = acc[mt][nt][1] + ba.y;
                float a10 = acc[mt][nt][2] + ba.x, a11 = acc[mt][nt][3] + ba.y;
                float g00 = acc[mt][nt+2][0] + bg.x, g01 = acc[mt][nt+2][1] + bg.y;
                float g10 = acc[mt][nt+2][2] + bg.x, g11 = acc[mt][nt+2][3] + bg.y;
                float2 o0 = make_float2(tf32r(a00 * (g00 / (1.f + __expf(-g00)))),
                                        tf32r(a01 * (g01 / (1.f + __expf(-g01)))));
                float2 o1 = make_float2(tf32r(a10 * (g10 / (1.f + __expf(-g10)))),
                                        tf32r(a11 * (g11 / (1.f + __expf(-g11)))));
                *(float2*)(C + (size_t)row0 * DFF_ + col) = o0;
                *(float2*)(C + (size_t)(row0 + 8) * DFF_ + col) = o1;
            }
        }
    }
}

// -------- QKV epilogue: 128 thr x float4 (2 RoPE pairs), __sincosf ----------
__global__ void qkv_post_kernel(const float* __restrict__ qkv,
                                const int*   __restrict__ x_type,
                                const float* __restrict__ type_emb,
                                const float* __restrict__ seq_order,
                                float* __restrict__ Q, float* __restrict__ Ko,
                                float* __restrict__ V) {
    int row = blockIdx.x;       // b*T + t
    int b = row >> 10;
    int t = row & (T_ - 1);
    int tid = threadIdx.x;      // 0..127 -> 4 dims d4..d4+3
    int d4 = tid * 4;

    int tq = x_type[b * (T_ + 1) + t];
    int tk = x_type[b * (T_ + 1) + t + 1];
    float pq = seq_order[b * (T_ + 1) + t];
    float pk = seq_order[b * (T_ + 1) + t + 1];

    const float* qr = qkv + (size_t)row * (3 * D_);
    float4 q = *(const float4*)(qr + d4);
    float4 k = *(const float4*)(qr + D_ + d4);
    float4 v = *(const float4*)(qr + 2 * D_ + d4);
    {
        float4 eq = *(const float4*)(type_emb + (size_t)tq * (2 * D_) + d4);
        float4 ek = *(const float4*)(type_emb + (size_t)tk * (2 * D_) + D_ + d4);
        q.x += eq.x; q.y += eq.y; q.z += eq.z; q.w += eq.w;
        k.x += ek.x; k.y += ek.y; k.z += ek.z; k.w += ek.w;
    }

    int h  = d4 >> 6;
    int dl = d4 & 63;
    if (dl < DPR_) {   // dl multiple of 4, so both pairs (dl,dl+1),(dl+2,dl+3) < 32
        const float c = -13.287712379549449f / 32.0f;
        float f0 = exp2f((float)dl * c);
        float f1 = exp2f((float)(dl + 2) * c);
        float s_, c_;
        __sincosf(pq * f0, &s_, &c_);
        { float n0 = q.x * c_ - q.y * s_; q.y = q.y * c_ + q.x * s_; q.x = n0; }
        __sincosf(pq * f1, &s_, &c_);
        { float n0 = q.z * c_ - q.w * s_; q.w = q.w * c_ + q.z * s_; q.z = n0; }
        __sincosf(pk * f0, &s_, &c_);
        { float n0 = k.x * c_ - k.y * s_; k.y = k.y * c_ + k.x * s_; k.x = n0; }
        __sincosf(pk * f1, &s_, &c_);
        { float n0 = k.z * c_ - k.w * s_; k.w = k.w * c_ + k.z * s_; k.z = n0; }
    }
    q.x = tf32r(q.x); q.y = tf32r(q.y); q.z = tf32r(q.z); q.w = tf32r(q.w);
    k.x = tf32r(k.x); k.y = tf32r(k.y); k.z = tf32r(k.z); k.w = tf32r(k.w);
    v.x = tf32r(v.x); v.y = tf32r(v.y); v.z = tf32r(v.z); v.w = tf32r(v.w);

    size_t o = (((size_t)(b * H_ + h)) * T_ + t) * HD_ + dl;
    *(float4*)(Q + o) = q;
    *(float4*)(Ko + o) = k;
    *(float4*)(V + o) = v;
}

// ===== tf32 flash attention (round-9: balanced q-tile pairs, 2-stage) ========
#define AT_PAD 68
#define AT_STAGE (2*64*AT_PAD)
#define AT_SMEM (2*AT_STAGE*4)

__global__ __launch_bounds__(256, 2)
void attn_tc_kernel(const float* __restrict__ Q, const float* __restrict__ Kc,
                    const float* __restrict__ V, float* __restrict__ O) {
    extern __shared__ float sm[];
    const unsigned sbase = (unsigned)__cvta_generic_to_shared(sm);
    const int pair = blockIdx.x;
    const int h  = blockIdx.y;
    const int b  = blockIdx.z;
    const int t = threadIdx.x;
    const int warp = t >> 5, lane = t & 31;
    const int g = lane >> 2, tig = lane & 3;
    const int wm = warp * 16;
    const size_t hb = ((size_t)(b * H_ + h)) * T_ * HD_;

    const int cr = t >> 4;
    const int cc4 = (t & 15) * 4;

    #pragma unroll 1
    for (int rep = 0; rep < 2; rep++) {
        const int qt = (rep == 0) ? pair : (7 - pair);
        const int qbase = qt * 128;

        unsigned qa[8][4];
        {
            const float* Qp = Q + hb + (size_t)(qbase + wm) * HD_;
            #pragma unroll
            for (int ks = 0; ks < 8; ks++) {
                int c0 = ks * 8 + tig;
                qa[ks][0] = __float_as_uint(Qp[g * 64 + c0] * 0.125f);
                qa[ks][1] = __float_as_uint(Qp[(g + 8) * 64 + c0] * 0.125f);
                qa[ks][2] = __float_as_uint(Qp[g * 64 + c0 + 4] * 0.125f);
                qa[ks][3] = __float_as_uint(Qp[(g + 8) * 64 + c0 + 4] * 0.125f);
            }
        }

        float m0 = -1e30f, m1 = -1e30f, l0 = 0.f, l1 = 0.f;
        float o[8][4];
        #pragma unroll
        for (int nt = 0; nt < 8; nt++)
            #pragma unroll
            for (int e = 0; e < 4; e++) o[nt][e] = 0.f;

        const int nT = qt * 2 + 2;

        {
            unsigned sK = sbase;
            unsigned sV = sK + 64 * AT_PAD * 4;
            const float* kp = Kc + hb;
            const float* vp = V + hb;
            #pragma unroll
            for (int j = 0; j < 4; j++) {
                int r = cr + 16 * j;
                cpasync16(sK + (r * AT_PAD + cc4) * 4, kp + r * 64 + cc4);
                cpasync16(sV + (r * AT_PAD + cc4) * 4, vp + r * 64 + cc4);
            }
            cpcommit();
        }

        int buf = 0;
        for (int kt = 0; kt < nT; kt++) {
            const int j0 = kt * 64;
            if (kt + 1 < nT) {
                unsigned sK = sbase + (buf ^ 1) * AT_STAGE * 4;
                unsigned sV = sK + 64 * AT_PAD * 4;
                const float* kp = Kc + hb + (size_t)(j0 + 64) * 64;
                const float* vp = V + hb + (size_t)(j0 + 64) * 64;
                #pragma unroll
                for (int j = 0; j < 4; j++) {
                    int r = cr + 16 * j;
                    cpasync16(sK + (r * AT_PAD + cc4) * 4, kp + r * 64 + cc4);
                    cpasync16(sV + (r * AT_PAD + cc4) * 4, vp + r * 64 + cc4);
                }
                cpcommit();
                asm volatile("cp.async.wait_group 1;");
            } else {
                asm volatile("cp.async.wait_group 0;");
            }
            __syncthreads();

            if (j0 <= qbase + wm + 15) {
                const unsigned* Ksmu = (const unsigned*)(sm + buf * AT_STAGE);
                const unsigned* Vsmu = Ksmu + 64 * AT_PAD;

                float s[8][4];
                #pragma unroll
                for (int nt = 0; nt < 8; nt++) {
                    float c0 = 0.f, c1 = 0.f, c2 = 0.f, c3 = 0.f;
                    const unsigned* kp = Ksmu + (nt * 8 + g) * AT_PAD + tig;
                    #pragma unroll
                    for (int ks = 0; ks < 8; ks++) {
                        mma_tf32(c0, c1, c2, c3,
                                 qa[ks][0], qa[ks][1], qa[ks][2], qa[ks][3],
                                 kp[ks * 8], kp[ks * 8 + 4]);
                    }
                    s[nt][0] = c0; s[nt][1] = c1; s[nt][2] = c2; s[nt][3] = c3;
                }

                const int r0 = qbase + wm + g, r1 = r0 + 8;
                if (j0 + 63 > qbase + wm) {
                    #pragma unroll
                    for (int nt = 0; nt < 8; nt++) {
                        int col = j0 + nt * 8 + 2 * tig;
                        if (col > r0)     s[nt][0] = -1e30f;
                        if (col + 1 > r0) s[nt][1] = -1e30f;
                        if (col > r1)     s[nt][2] = -1e30f;
                        if (col + 1 > r1) s[nt][3] = -1e30f;
                    }
                }

                float mx0 = -1e30f, mx1 = -1e30f;
                #pragma unroll
                for (int nt = 0; nt < 8; nt++) {
                    mx0 = fmaxf(mx0, fmaxf(s[nt][0], s[nt][1]));
                    mx1 = fmaxf(mx1, fmaxf(s[nt][2], s[nt][3]));
                }
                mx0 = fmaxf(mx0, __shfl_xor_sync(0xffffffffu, mx0, 1));
                mx0 = fmaxf(mx0, __shfl_xor_sync(0xffffffffu, mx0, 2));
                mx1 = fmaxf(mx1, __shfl_xor_sync(0xffffffffu, mx1, 1));
                mx1 = fmaxf(mx1, __shfl_xor_sync(0xffffffffu, mx1, 2));
                float nm0 = fmaxf(m0, mx0), nm1 = fmaxf(m1, mx1);
                float sc0 = __expf(m0 - nm0), sc1 = __expf(m1 - nm1);
                m0 = nm0; m1 = nm1;
                float sum0 = 0.f, sum1 = 0.f;
                #pragma unroll
                for (int nt = 0; nt < 8; nt++) {
                    s[nt][0] = __expf(s[nt][0] - m0); sum0 += s[nt][0];
                    s[nt][1] = __expf(s[nt][1] - m0); sum0 += s[nt][1];
                    s[nt][2] = __expf(s[nt][2] - m1); sum1 += s[nt][2];
                    s[nt][3] = __expf(s[nt][3] - m1); sum1 += s[nt][3];
                }
                l0 = l0 * sc0 + sum0;
                l1 = l1 * sc1 + sum1;
                #pragma unroll
                for (int nt = 0; nt < 8; nt++) {
                    o[nt][0] *= sc0; o[nt][1] *= sc0;
                    o[nt][2] *= sc1; o[nt][3] *= sc1;
                }

                #pragma unroll
                for (int ks = 0; ks < 8; ks++) {
                    const int srcA = (lane & 0x1c) | (tig >> 1);
                    float v00 = __shfl_sync(0xffffffffu, s[ks][0], srcA);
                    float v01 = __shfl_sync(0xffffffffu, s[ks][1], srcA);
                    float a0f = (tig & 1) ? v01 : v00;
                    float v02 = __shfl_sync(0xffffffffu, s[ks][0], srcA + 2);
                    float v03 = __shfl_sync(0xffffffffu, s[ks][1], srcA + 2);
                    float a2f = (tig & 1) ? v03 : v02;
                    float w00 = __shfl_sync(0xffffffffu, s[ks][2], srcA);
                    float w01 = __shfl_sync(0xffffffffu, s[ks][3], srcA);
                    float a1f = (tig & 1) ? w01 : w00;
                    float w02 = __shfl_sync(0xffffffffu, s[ks][2], srcA + 2);
                    float w03 = __shfl_sync(0xffffffffu, s[ks][3], srcA + 2);
                    float a3f = (tig & 1) ? w03 : w02;
                    unsigned a0 = rna_tf32f(a0f), a1 = rna_tf32f(a1f);
                    unsigned a2 = rna_tf32f(a2f), a3 = rna_tf32f(a3f);
                    const unsigned* vp = Vsmu + (ks * 8 + tig) * AT_PAD + g;
                    #pragma unroll
                    for (int nt = 0; nt < 8; nt++) {
                        mma_tf32(o[nt][0], o[nt][1], o[nt][2], o[nt][3],
                                 a0, a1, a2, a3,
                                 vp[nt * 8], vp[4 * AT_PAD + nt * 8]);
                    }
                }
            }
            __syncthreads();
            buf ^= 1;
        }

        l0 += __shfl_xor_sync(0xffffffffu, l0, 1);
        l0 += __shfl_xor_sync(0xffffffffu, l0, 2);
        l1 += __shfl_xor_sync(0xffffffffu, l1, 1);
        l1 += __shfl_xor_sync(0xffffffffu, l1, 2);
        float inv0 = 1.0f / l0, inv1 = 1.0f / l1;
        float* Op = O + hb + (size_t)(qbase + wm) * HD_;
        #pragma unroll
        for (int nt = 0; nt < 8; nt++) {
            int col = nt * 8 + 2 * tig;
            *(float2*)(Op + g * 64 + col) =
                make_float2(o[nt][0] * inv0, o[nt][1] * inv0);
            *(float2*)(Op + (g + 8) * 64 + col) =
                make_float2(o[nt][2] * inv1, o[nt][3] * inv1);
        }
    }
}

// ---------------- launch ----------------
extern "C" void kernel_launch(void* const* d_in, const int* in_sizes, int n_in,
                              void* d_out, int out_size) {
    (void)in_sizes; (void)n_in; (void)out_size;
    const int*   x_type   = (const int*)  d_in[0];
    const float* x_value  = (const float*)d_in[1];
    const float* seq_ord  = (const float*)d_in[2];
    const float* W_attn   = (const float*)d_in[3];
    const float* type_emb = (const float*)d_in[4];
    const float* ln1_g    = (const float*)d_in[5];
    const float* ln1_b    = (const float*)d_in[6];
    const float* ln2_g    = (const float*)d_in[7];
    const float* ln2_b    = (const float*)d_in[8];
    const float* W1       = (const float*)d_in[9];
    const float* b1       = (const float*)d_in[10];
    const float* W2       = (const float*)d_in[11];
    const float* b2       = (const float*)d_in[12];
    float* out = (float*)d_out;

    float *p_h, *p_qkv, *p_q, *p_k, *p_v, *p_ao, *p_xres, *p_h2, *p_g;
    float *p_wa, *p_w1, *p_w2;
    cudaGetSymbolAddress((void**)&p_h,    g_h);
    cudaGetSymbolAddress((void**)&p_qkv,  g_qkv);
    cudaGetSymbolAddress((void**)&p_q,    g_q);
    cudaGetSymbolAddress((void**)&p_k,    g_k);
    cudaGetSymbolAddress((void**)&p_v,    g_v);
    cudaGetSymbolAddress((void**)&p_ao,   g_ao);
    cudaGetSymbolAddress((void**)&p_xres, g_xres);
    cudaGetSymbolAddress((void**)&p_h2,   g_h2);
    cudaGetSymbolAddress((void**)&p_g,    g_g);
    cudaGetSymbolAddress((void**)&p_wa,   g_wa);
    cudaGetSymbolAddress((void**)&p_w1,   g_w1);
    cudaGetSymbolAddress((void**)&p_w2,   g_w2);

    cudaFuncSetAttribute(tf32_gemm<0, false, false>,
                         cudaFuncAttributeMaxDynamicSharedMemorySize, GSMEM_BYTES);
    cudaFuncSetAttribute(tf32_gemm<2, true, false>,
                         cudaFuncAttributeMaxDynamicSharedMemorySize, GSMEM_BYTES);
    cudaFuncSetAttribute(tf32_gemm<0, true, true>,
                         cudaFuncAttributeMaxDynamicSharedMemorySize, GSMEM_BYTES);
    cudaFuncSetAttribute(attn_tc_kernel,
                         cudaFuncAttributeMaxDynamicSharedMemorySize, AT_SMEM);

    // 0. pre-round all weights to tf32 in ONE launch
    {
        const int n4 = D_*3*D_/4 + D_*2*DFF_/4 + DFF_*D_/4;
        round3_tf32_kernel<<<(n4 + 255)/256, 256>>>(W_attn, p_wa, W1, p_w1, W2, p_w2);
    }
    // 1. LN1 (tf32-rounded output)
    ln_kernel<<<ROWS_, 128>>>(x_value, ln1_g, ln1_b, p_h);
    // 2. QKV GEMM: [8192,512] @ [512,1536]
    tf32_gemm<0, false, false><<<dim3(12, ROWS_ / 128), 256, GSMEM_BYTES>>>(
        p_h, p_wa, nullptr, nullptr, p_qkv, ROWS_, 3 * D_, D_);
    // 3. emb + RoPE + transpose (tf32-rounded Q/K/V, float4-vectorized)
    qkv_post_kernel<<<ROWS_, 128>>>(p_qkv, x_type, type_emb, seq_ord, p_q, p_k, p_v);
    // 4. causal flash attention (balanced q-tile pairs)
    attn_tc_kernel<<<dim3(4, H_, B_), 256, AT_SMEM>>>(p_q, p_k, p_v, p_ao);
    // 5. residual + LN2
    addres_ln2_kernel<<<ROWS_, 128>>>(x_value, p_ao, ln2_g, ln2_b, p_xres, p_h2);
    // 6. FFN GEMM1 + fused bias + SwiGLU epilogue -> g (tf32-rounded)
    tf32_gemm<2, true, false><<<dim3(16, ROWS_ / 128), 256, GSMEM_BYTES>>>(
        p_h2, p_w1, b1, nullptr, p_g, ROWS_, 2 * DFF_, D_);
    // 7. FFN GEMM2 + bias + residual -> out
    tf32_gemm<0, true, true><<<dim3(4, ROWS_ / 128), 256, GSMEM_BYTES>>>(
        p_g, p_w2, b2, p_xres, out, ROWS_, D_, DFF_);
}

// round 15
// speedup vs baseline: 1.0719x; 1.0013x over previous
#include <cuda_runtime.h>
#include <cuda_bf16.h>
#include <math.h>

// Problem constants
#define B_  8
#define T_  1024
#define D_  512
#define H_  8
#define HD_ 64
#define DFF_ 1024
#define DPR_ 32
#define ROWS_ (B_*T_)   // 8192

// ---------------- scratch (device globals; no allocation allowed) ----------------
__device__ float g_h   [ROWS_*D_];        // ln1 output (tf32-rounded)
__device__ float g_q   [B_*H_*T_*HD_];    // [B,H,T,HD] (tf32-rounded)
__device__ float g_k   [B_*H_*T_*HD_];    // (tf32-rounded)
__device__ float g_v   [B_*H_*T_*HD_];    // (tf32-rounded)
__device__ float g_ao  [B_*H_*T_*HD_];    // attention out (full fp32)
__device__ float g_xres[ROWS_*D_];        // x_value + attn (full fp32)
__device__ float g_h2  [ROWS_*D_];        // ln2 output (tf32-rounded)
__device__ float g_g   [ROWS_*DFF_];      // swiglu output (tf32-rounded)
__device__ float g_wa  [D_*3*D_];         // W_attn tf32-rounded
__device__ float g_w1  [D_*2*DFF_];       // W1 tf32-rounded
__device__ float g_w2  [DFF_*D_];         // W2 tf32-rounded

// ---------------- helpers ----------------
__device__ __forceinline__ void cpasync16(unsigned s, const void* g) {
    asm volatile("cp.async.cg.shared.global [%0], [%1], 16;" :: "r"(s), "l"(g));
}
__device__ __forceinline__ void cpcommit() {
    asm volatile("cp.async.commit_group;");
}
__device__ __forceinline__ unsigned rna_tf32f(float f) {
    unsigned r;
    asm("cvt.rna.tf32.f32 %0, %1;" : "=r"(r) : "f"(f));
    return r;
}
__device__ __forceinline__ float tf32r(float f) {
    return __uint_as_float(rna_tf32f(f));
}
__device__ __forceinline__ void mma_tf32(float& c0, float& c1, float& c2, float& c3,
                                         unsigned a0, unsigned a1, unsigned a2, unsigned a3,
                                         unsigned b0, unsigned b1) {
    asm volatile(
        "mma.sync.aligned.m16n8k8.row.col.f32.tf32.tf32.f32 "
        "{%0,%1,%2,%3}, {%4,%5,%6,%7}, {%8,%9}, {%0,%1,%2,%3};"
        : "+f"(c0), "+f"(c1), "+f"(c2), "+f"(c3)
        : "r"(a0), "r"(a1), "r"(a2), "r"(a3), "r"(b0), "r"(b1));
}

__device__ __forceinline__ void blockReduce2_128(float& a, float& b) {
    #pragma unroll
    for (int o = 16; o > 0; o >>= 1) {
        a += __shfl_xor_sync(0xffffffffu, a, o);
        b += __shfl_xor_sync(0xffffffffu, b, o);
    }
    __shared__ float sa[4], sb[4];
    int w = threadIdx.x >> 5;
    if ((threadIdx.x & 31) == 0) { sa[w] = a; sb[w] = b; }
    __syncthreads();
    a = sa[0] + sa[1] + sa[2] + sa[3];
    b = sb[0] + sb[1] + sb[2] + sb[3];
}

// ---------------- tf32 pre-round of all three weights (single launch) --------
__global__ void round3_tf32_kernel(const float* __restrict__ wa_in, float* __restrict__ wa_out,
                                   const float* __restrict__ w1_in, float* __restrict__ w1_out,
                                   const float* __restrict__ w2_in, float* __restrict__ w2_out) {
    const int n_a = D_*3*D_/4, n_1 = D_*2*DFF_/4, n_2 = DFF_*D_/4;
    int i = blockIdx.x * blockDim.x + threadIdx.x;
    const float4* src; float4* dst; int j;
    if (i < n_a)             { src = (const float4*)wa_in; dst = (float4*)wa_out; j = i; }
    else if (i < n_a + n_1)  { src = (const float4*)w1_in; dst = (float4*)w1_out; j = i - n_a; }
    else if (i < n_a + n_1 + n_2) { src = (const float4*)w2_in; dst = (float4*)w2_out; j = i - n_a - n_1; }
    else return;
    float4 v = src[j];
    v.x = tf32r(v.x); v.y = tf32r(v.y); v.z = tf32r(v.z); v.w = tf32r(v.w);
    dst[j] = v;
}

// ---------------- LayerNorm (output tf32-rounded: feeds GEMM A) ----------------
__global__ void ln_kernel(const float* __restrict__ x,
                          const float* __restrict__ g,
                          const float* __restrict__ bta,
                          float* __restrict__ out) {
    int row = blockIdx.x;
    int tid = threadIdx.x;
    const float4* xr = (const float4*)(x + (size_t)row * D_);
    float4 v = xr[tid];
    float s  = v.x + v.y + v.z + v.w;
    float sq = v.x*v.x + v.y*v.y + v.z*v.z + v.w*v.w;
    blockReduce2_128(s, sq);
    float mean = s * (1.0f / D_);
    float var  = sq * (1.0f / D_) - mean * mean;
    float inv  = rsqrtf(var + 1e-5f);
    float4 gg = ((const float4*)g)[tid];
    float4 bb = ((const float4*)bta)[tid];
    float4 o;
    o.x = tf32r((v.x - mean) * inv * gg.x + bb.x);
    o.y = tf32r((v.y - mean) * inv * gg.y + bb.y);
    o.z = tf32r((v.z - mean) * inv * gg.z + bb.z);
    o.w = tf32r((v.w - mean) * inv * gg.w + bb.w);
    ((float4*)(out + (size_t)row * D_))[tid] = o;
}

// ---------------- residual add + LayerNorm2 (h2 tf32-rounded; xres full) ------
__global__ void addres_ln2_kernel(const float* __restrict__ xv,
                                  const float* __restrict__ ao,
                                  const float* __restrict__ g,
                                  const float* __restrict__ bta,
                                  float* __restrict__ xres,
                                  float* __restrict__ h2) {
    int row = blockIdx.x;
    int b = row >> 10;
    int t = row & (T_ - 1);
    int tid = threadIdx.x;
    int d  = tid * 4;
    int h  = d >> 6;
    int dl = d & 63;
    float4 a = *(const float4*)(ao + ((((size_t)(b * H_ + h)) * T_ + t) * HD_ + dl));
    float4 v = ((const float4*)(xv + (size_t)row * D_))[tid];
    v.x += a.x; v.y += a.y; v.z += a.z; v.w += a.w;
    ((float4*)(xres + (size_t)row * D_))[tid] = v;
    float s  = v.x + v.y + v.z + v.w;
    float sq = v.x*v.x + v.y*v.y + v.z*v.z + v.w*v.w;
    blockReduce2_128(s, sq);
    float mean = s * (1.0f / D_);
    float var  = sq * (1.0f / D_) - mean * mean;
    float inv  = rsqrtf(var + 1e-5f);
    float4 gg = ((const float4*)g)[tid];
    float4 bb = ((const float4*)bta)[tid];
    float4 o;
    o.x = tf32r((v.x - mean) * inv * gg.x + bb.x);
    o.y = tf32r((v.y - mean) * inv * gg.y + bb.y);
    o.z = tf32r((v.z - mean) * inv * gg.z + bb.z);
    o.w = tf32r((v.w - mean) * inv * gg.w + bb.w);
    ((float4*)(h2 + (size_t)row * D_))[tid] = o;
}

// ========== tf32 GEMM (round-9 mainloop: 128x128, warp 64x32, 2-stage) =======
// EPI 0: plain (+bias/+res).  EPI 1: QKV (emb + RoPE(__sincosf) + transpose).
// EPI 2: SwiGLU epilogue (B cols remapped).
#define ASTRIDE 36
#define BSTRIDE 136
#define STAGE_WORDS (128*ASTRIDE + 32*BSTRIDE)   // 8960
#define GSMEM_BYTES (2 * STAGE_WORDS * 4)        // 71680

template<int EPI, bool HAS_BIAS, bool HAS_RES>
__global__ __launch_bounds__(256, 2)
void tf32_gemm(const float* __restrict__ A, const float* __restrict__ Bm,
               const float* __restrict__ bias, const float* __restrict__ res,
               float* __restrict__ C, int M, int N, int K,
               const int* __restrict__ x_type = nullptr,
               const float* __restrict__ type_emb = nullptr,
               const float* __restrict__ seq_order = nullptr,
               float* __restrict__ Qo = nullptr,
               float* __restrict__ Ko = nullptr,
               float* __restrict__ Vo = nullptr) {
    extern __shared__ float smem[];
    const unsigned sbase = (unsigned)__cvta_generic_to_shared(smem);
    const int t = threadIdx.x;
    const int bx = blockIdx.x;
    const int m0 = blockIdx.y * 128;
    const int n0 = bx * 128;
    const int warp = t >> 5, lane = t & 31;
    const int wm = (warp >> 2) * 64;
    const int wn32 = (warp & 3) * 32;
    const int wn16 = (warp & 3) * 16;
    const int g  = lane >> 2, tig = lane & 3;

    float acc[4][4][4];
    #pragma unroll
    for (int i = 0; i < 4; i++)
        #pragma unroll
        for (int j = 0; j < 4; j++)
            #pragma unroll
            for (int e = 0; e < 4; e++) acc[i][j][e] = 0.f;

    const int mA = t >> 3, k4 = t & 7;
    const int kB = t >> 5, n4 = t & 31;
    int bcol;
    if (EPI == 2) bcol = (n4 < 16) ? bx*64 + n4*4 : DFF_ + bx*64 + (n4-16)*4;
    else          bcol = n0 + n4*4;

    int bfcol[4];
    #pragma unroll
    for (int nt = 0; nt < 4; nt++)
        bfcol[nt] = (EPI == 2) ? ((nt < 2) ? wn16 + nt*8 : 64 + wn16 + (nt-2)*8)
                               : wn32 + nt*8;

    {
        unsigned sA = sbase;
        unsigned sB = sbase + 128*ASTRIDE*4;
        #pragma unroll
        for (int j = 0; j < 4; j++) {
            int ma = mA + 32*j;
            cpasync16(sA + (ma*ASTRIDE + k4*4)*4, A + (size_t)(m0 + ma)*K + k4*4);
            int kb = kB + 8*j;
            cpasync16(sB + (kb*BSTRIDE + n4*4)*4, Bm + (size_t)kb*N + bcol);
        }
        cpcommit();
    }

    const int nIter = K >> 5;
    int buf = 0;
    for (int it = 0; it < nIter; ++it) {
        if (it + 1 < nIter) {
            int k0 = (it + 1) << 5;
            unsigned sA = sbase + (buf ^ 1) * STAGE_WORDS * 4;
            unsigned sB = sA + 128*ASTRIDE*4;
            #pragma unroll
            for (int j = 0; j < 4; j++) {
                int ma = mA + 32*j;
                cpasync16(sA + (ma*ASTRIDE + k4*4)*4,
                          A + (size_t)(m0 + ma)*K + k0 + k4*4);
                int kb = kB + 8*j;
                cpasync16(sB + (kb*BSTRIDE + n4*4)*4,
                          Bm + (size_t)(k0 + kb)*N + bcol);
            }
            cpcommit();
            asm volatile("cp.async.wait_group 1;");
        } else {
            asm volatile("cp.async.wait_group 0;");
        }
        __syncthreads();

        const unsigned* Asu = (const unsigned*)(smem + buf * STAGE_WORDS);
        const unsigned* Bsu = Asu + 128*ASTRIDE;

        #pragma unroll
        for (int ks = 0; ks < 4; ks++) {
            unsigned a[4][4], b[4][2];
            #pragma unroll
            for (int mt = 0; mt < 4; mt++) {
                const unsigned* p = Asu + (wm + mt*16 + g)*ASTRIDE + ks*8 + tig;
                a[mt][0] = p[0];
                a[mt][1] = p[8*ASTRIDE];
                a[mt][2] = p[4];
                a[mt][3] = p[8*ASTRIDE + 4];
            }
            #pragma unroll
            for (int nt = 0; nt < 4; nt++) {
                const unsigned* p = Bsu + (ks*8 + tig)*BSTRIDE + bfcol[nt] + g;
                b[nt][0] = p[0];
                b[nt][1] = p[4*BSTRIDE];
            }
            #pragma unroll
            for (int mt = 0; mt < 4; mt++)
                #pragma unroll
                for (int nt = 0; nt < 4; nt++)
                    mma_tf32(acc[mt][nt][0], acc[mt][nt][1],
                             acc[mt][nt][2], acc[mt][nt][3],
                             a[mt][0], a[mt][1], a[mt][2], a[mt][3],
                             b[nt][0], b[nt][1]);
        }
        __syncthreads();
        buf ^= 1;
    }

    // ================== epilogues ==================
    if (EPI == 0) {
        #pragma unroll
        for (int mt = 0; mt < 4; mt++) {
            int row0 = m0 + wm + mt * 16 + g;
            #pragma unroll
            for (int nt = 0; nt < 4; nt++) {
                int col = n0 + wn32 + nt * 8 + tig * 2;
                float2 v0 = make_float2(acc[mt][nt][0], acc[mt][nt][1]);
                float2 v1 = make_float2(acc[mt][nt][2], acc[mt][nt][3]);
                if (HAS_BIAS) {
                    float2 bb = *(const float2*)(bias + col);
                    v0.x += bb.x; v0.y += bb.y; v1.x += bb.x; v1.y += bb.y;
                }
                if (HAS_RES) {
                    float2 r0 = *(const float2*)(res + (size_t)row0 * N + col);
                    float2 r1 = *(const float2*)(res + (size_t)(row0 + 8) * N + col);
                    v0.x += r0.x; v0.y += r0.y; v1.x += r1.x; v1.y += r1.y;
                }
                *(float2*)(C + (size_t)row0 * N + col) = v0;
                *(float2*)(C + (size_t)(row0 + 8) * N + col) = v1;
            }
        }
    } else if (EPI == 1) {
        // QKV epilogue: tile is purely q (seg 0), k (seg 1), or v (seg 2).
        const int seg = n0 >> 9;
        int cl_nt[4], h_nt[4], dl_nt[4];
        float f_nt[4];
        #pragma unroll
        for (int nt = 0; nt < 4; nt++) {
            int c = n0 + wn32 + nt*8 + 2*tig;
            cl_nt[nt] = c & 511;
            h_nt[nt]  = cl_nt[nt] >> 6;
            dl_nt[nt] = cl_nt[nt] & 63;
            f_nt[nt]  = exp2f((float)dl_nt[nt] * (-13.287712379549449f / 32.0f));
        }
        float* dst = (seg == 0) ? Qo : (seg == 1) ? Ko : Vo;
        #pragma unroll
        for (int mt = 0; mt < 4; mt++) {
            #pragma unroll
            for (int half = 0; half < 2; half++) {
                int row = m0 + wm + mt*16 + g + half*8;
                int bb = row >> 10, tt = row & 1023;
                int typ = 0; float pos = 0.f;
                if (seg < 2) {
                    int idx = bb * (T_ + 1) + tt + seg;   // q uses t, k uses t+1
                    typ = x_type[idx];
                    pos = seq_order[idx];
                }
                #pragma unroll
                for (int nt = 0; nt < 4; nt++) {
                    float v0 = acc[mt][nt][half*2];
                    float v1 = acc[mt][nt][half*2 + 1];
                    if (seg < 2) {
                        float2 e = *(const float2*)(type_emb + (size_t)typ * (2*D_)
                                                    + seg * D_ + cl_nt[nt]);
                        v0 += e.x; v1 += e.y;
                        if (dl_nt[nt] < DPR_) {
                            float s_, c_;
                            __sincosf(pos * f_nt[nt], &s_, &c_);
                            float nv0 = v0 * c_ - v1 * s_;
                            v1 = v1 * c_ + v0 * s_;
                            v0 = nv0;
                        }
                    }
                    *(float2*)(dst + (((size_t)(bb * H_ + h_nt[nt])) * T_ + tt) * HD_
                               + dl_nt[nt]) = make_float2(tf32r(v0), tf32r(v1));
                }
            }
        }
    } else {  // EPI == 2: g = (a + ba) * silu(gate + bg), tf32-rounded store
        #pragma unroll
        for (int mt = 0; mt < 4; mt++) {
            int row0 = m0 + wm + mt * 16 + g;
            #pragma unroll
            for (int nt = 0; nt < 2; nt++) {
                int col = bx*64 + wn16 + nt*8 + 2*tig;
                float2 ba = *(const float2*)(bias + col);
                float2 bg = *(const float2*)(bias + DFF_ + col);
                float a00 = acc[mt][nt][0] + ba.x, a01 = acc[mt][nt][1] + ba.y;
                float a10 = acc[mt][nt][2] + ba.x, a11 = acc[mt][nt][3] + ba.y;
                float g00 = acc[mt][nt+2][0] + bg.x, g01 = acc[mt][nt+2][1] + bg.y;
                float g10 = acc[mt][nt+2][2] + bg.x, g11 = acc[mt][nt+2][3] + bg.y;
                float2 o0 = make_float2(tf32r(a00 * (g00 / (1.f + __expf(-g00)))),
                                        tf32r(a01 * (g01 / (1.f + __expf(-g01)))));
                float2 o1 = make_float2(tf32r(a10 * (g10 / (1.f + __expf(-g10)))),
                                        tf32r(a11 * (g11 / (1.f + __expf(-g11)))));
                *(float2*)(C + (size_t)row0 * DFF_ + col) = o0;
                *(float2*)(C + (size_t)(row0 + 8) * DFF_ + col) = o1;
            }
        }
    }
}

// ===== tf32 flash attention (round-9: balanced q-tile pairs, 2-stage) ========
#define AT_PAD 68
#define AT_STAGE (2*64*AT_PAD)
#define AT_SMEM (2*AT_STAGE*4)

__global__ __launch_bounds__(256, 2)
void attn_tc_kernel(const float* __restrict__ Q, const float* __restrict__ Kc,
                    const float* __restrict__ V, float* __restrict__ O) {
    extern __shared__ float sm[];
    const unsigned sbase = (unsigned)__cvta_generic_to_shared(sm);
    const int pair = blockIdx.x;
    const int h  = blockIdx.y;
    const int b  = blockIdx.z;
    const int t = threadIdx.x;
    const int warp = t >> 5, lane = t & 31;
    const int g = lane >> 2, tig = lane & 3;
    const int wm = warp * 16;
    const size_t hb = ((size_t)(b * H_ + h)) * T_ * HD_;

    const int cr = t >> 4;
    const int cc4 = (t & 15) * 4;

    #pragma unroll 1
    for (int rep = 0; rep < 2; rep++) {
        const int qt = (rep == 0) ? pair : (7 - pair);
        const int qbase = qt * 128;

        unsigned qa[8][4];
        {
            const float* Qp = Q + hb + (size_t)(qbase + wm) * HD_;
            #pragma unroll
            for (int ks = 0; ks < 8; ks++) {
                int c0 = ks * 8 + tig;
                qa[ks][0] = __float_as_uint(Qp[g * 64 + c0] * 0.125f);
                qa[ks][1] = __float_as_uint(Qp[(g + 8) * 64 + c0] * 0.125f);
                qa[ks][2] = __float_as_uint(Qp[g * 64 + c0 + 4] * 0.125f);
                qa[ks][3] = __float_as_uint(Qp[(g + 8) * 64 + c0 + 4] * 0.125f);
            }
        }

        float m0 = -1e30f, m1 = -1e30f, l0 = 0.f, l1 = 0.f;
        float o[8][4];
        #pragma unroll
        for (int nt = 0; nt < 8; nt++)
            #pragma unroll
            for (int e = 0; e < 4; e++) o[nt][e] = 0.f;

        const int nT = qt * 2 + 2;

        {
            unsigned sK = sbase;
            unsigned sV = sK + 64 * AT_PAD * 4;
            const float* kp = Kc + hb;
            const float* vp = V + hb;
            #pragma unroll
            for (int j = 0; j < 4; j++) {
                int r = cr + 16 * j;
                cpasync16(sK + (r * AT_PAD + cc4) * 4, kp + r * 64 + cc4);
                cpasync16(sV + (r * AT_PAD + cc4) * 4, vp + r * 64 + cc4);
            }
            cpcommit();
        }

        int buf = 0;
        for (int kt = 0; kt < nT; kt++) {
            const int j0 = kt * 64;
            if (kt + 1 < nT) {
                unsigned sK = sbase + (buf ^ 1) * AT_STAGE * 4;
                unsigned sV = sK + 64 * AT_PAD * 4;
                const float* kp = Kc + hb + (size_t)(j0 + 64) * 64;
                const float* vp = V + hb + (size_t)(j0 + 64) * 64;
                #pragma unroll
                for (int j = 0; j < 4; j++) {
                    int r = cr + 16 * j;
                    cpasync16(sK + (r * AT_PAD + cc4) * 4, kp + r * 64 + cc4);
                    cpasync16(sV + (r * AT_PAD + cc4) * 4, vp + r * 64 + cc4);
                }
                cpcommit();
                asm volatile("cp.async.wait_group 1;");
            } else {
                asm volatile("cp.async.wait_group 0;");
            }
            __syncthreads();

            if (j0 <= qbase + wm + 15) {
                const unsigned* Ksmu = (const unsigned*)(sm + buf * AT_STAGE);
                const unsigned* Vsmu = Ksmu + 64 * AT_PAD;

                float s[8][4];
                #pragma unroll
                for (int nt = 0; nt < 8; nt++) {
                    float c0 = 0.f, c1 = 0.f, c2 = 0.f, c3 = 0.f;
                    const unsigned* kp = Ksmu + (nt * 8 + g) * AT_PAD + tig;
                    #pragma unroll
                    for (int ks = 0; ks < 8; ks++) {
                        mma_tf32(c0, c1, c2, c3,
                                 qa[ks][0], qa[ks][1], qa[ks][2], qa[ks][3],
                                 kp[ks * 8], kp[ks * 8 + 4]);
                    }
                    s[nt][0] = c0; s[nt][1] = c1; s[nt][2] = c2; s[nt][3] = c3;
                }

                const int r0 = qbase + wm + g, r1 = r0 + 8;
                if (j0 + 63 > qbase + wm) {
                    #pragma unroll
                    for (int nt = 0; nt < 8; nt++) {
                        int col = j0 + nt * 8 + 2 * tig;
                        if (col > r0)     s[nt][0] = -1e30f;
                        if (col + 1 > r0) s[nt][1] = -1e30f;
                        if (col > r1)     s[nt][2] = -1e30f;
                        if (col + 1 > r1) s[nt][3] = -1e30f;
                    }
                }

                float mx0 = -1e30f, mx1 = -1e30f;
                #pragma unroll
                for (int nt = 0; nt < 8; nt++) {
                    mx0 = fmaxf(mx0, fmaxf(s[nt][0], s[nt][1]));
                    mx1 = fmaxf(mx1, fmaxf(s[nt][2], s[nt][3]));
                }
                mx0 = fmaxf(mx0, __shfl_xor_sync(0xffffffffu, mx0, 1));
                mx0 = fmaxf(mx0, __shfl_xor_sync(0xffffffffu, mx0, 2));
                mx1 = fmaxf(mx1, __shfl_xor_sync(0xffffffffu, mx1, 1));
                mx1 = fmaxf(mx1, __shfl_xor_sync(0xffffffffu, mx1, 2));
                float nm0 = fmaxf(m0, mx0), nm1 = fmaxf(m1, mx1);
                float sc0 = __expf(m0 - nm0), sc1 = __expf(m1 - nm1);
                m0 = nm0; m1 = nm1;
                float sum0 = 0.f, sum1 = 0.f;
                #pragma unroll
                for (int nt = 0; nt < 8; nt++) {
                    s[nt][0] = __expf(s[nt][0] - m0); sum0 += s[nt][0];
                    s[nt][1] = __expf(s[nt][1] - m0); sum0 += s[nt][1];
                    s[nt][2] = __expf(s[nt][2] - m1); sum1 += s[nt][2];
                    s[nt][3] = __expf(s[nt][3] - m1); sum1 += s[nt][3];
                }
                l0 = l0 * sc0 + sum0;
                l1 = l1 * sc1 + sum1;
                #pragma unroll
                for (int nt = 0; nt < 8; nt++) {
                    o[nt][0] *= sc0; o[nt][1] *= sc0;
                    o[nt][2] *= sc1; o[nt][3] *= sc1;
                }

                #pragma unroll
                for (int ks = 0; ks < 8; ks++) {
                    const int srcA = (lane & 0x1c) | (tig >> 1);
                    float v00 = __shfl_sync(0xffffffffu, s[ks][0], srcA);
                    float v01 = __shfl_sync(0xffffffffu, s[ks][1], srcA);
                    float a0f = (tig & 1) ? v01 : v00;
                    float v02 = __shfl_sync(0xffffffffu, s[ks][0], srcA + 2);
                    float v03 = __shfl_sync(0xffffffffu, s[ks][1], srcA + 2);
                    float a2f = (tig & 1) ? v03 : v02;
                    float w00 = __shfl_sync(0xffffffffu, s[ks][2], srcA);
                    float w01 = __shfl_sync(0xffffffffu, s[ks][3], srcA);
                    float a1f = (tig & 1) ? w01 : w00;
                    float w02 = __shfl_sync(0xffffffffu, s[ks][2], srcA + 2);
                    float w03 = __shfl_sync(0xffffffffu, s[ks][3], srcA + 2);
                    float a3f = (tig & 1) ? w03 : w02;
                    unsigned a0 = rna_tf32f(a0f), a1 = rna_tf32f(a1f);
                    unsigned a2 = rna_tf32f(a2f), a3 = rna_tf32f(a3f);
                    const unsigned* vp = Vsmu + (ks * 8 + tig) * AT_PAD + g;
                    #pragma unroll
                    for (int nt = 0; nt < 8; nt++) {
                        mma_tf32(o[nt][0], o[nt][1], o[nt][2], o[nt][3],
                                 a0, a1, a2, a3,
                                 vp[nt * 8], vp[4 * AT_PAD + nt * 8]);
                    }
                }
            }
            __syncthreads();
            buf ^= 1;
        }

        l0 += __shfl_xor_sync(0xffffffffu, l0, 1);
        l0 += __shfl_xor_sync(0xffffffffu, l0, 2);
        l1 += __shfl_xor_sync(0xffffffffu, l1, 1);
        l1 += __shfl_xor_sync(0xffffffffu, l1, 2);
        float inv0 = 1.0f / l0, inv1 = 1.0f / l1;
        float* Op = O + hb + (size_t)(qbase + wm) * HD_;
        #pragma unroll
        for (int nt = 0; nt < 8; nt++) {
            int col = nt * 8 + 2 * tig;
            *(float2*)(Op + g * 64 + col) =
                make_float2(o[nt][0] * inv0, o[nt][1] * inv0);
            *(float2*)(Op + (g + 8) * 64 + col) =
                make_float2(o[nt][2] * inv1, o[nt][3] * inv1);
        }
    }
}

// ---------------- launch ----------------
extern "C" void kernel_launch(void* const* d_in, const int* in_sizes, int n_in,
                              void* d_out, int out_size) {
    (void)in_sizes; (void)n_in; (void)out_size;
    const int*   x_type   = (const int*)  d_in[0];
    const float* x_value  = (const float*)d_in[1];
    const float* seq_ord  = (const float*)d_in[2];
    const float* W_attn   = (const float*)d_in[3];
    const float* type_emb = (const float*)d_in[4];
    const float* ln1_g    = (const float*)d_in[5];
    const float* ln1_b    = (const float*)d_in[6];
    const float* ln2_g    = (const float*)d_in[7];
    const float* ln2_b    = (const float*)d_in[8];
    const float* W1       = (const float*)d_in[9];
    const float* b1       = (const float*)d_in[10];
    const float* W2       = (const float*)d_in[11];
    const float* b2       = (const float*)d_in[12];
    float* out = (float*)d_out;

    float *p_h, *p_q, *p_k, *p_v, *p_ao, *p_xres, *p_h2, *p_g;
    float *p_wa, *p_w1, *p_w2;
    cudaGetSymbolAddress((void**)&p_h,    g_h);
    cudaGetSymbolAddress((void**)&p_q,    g_q);
    cudaGetSymbolAddress((void**)&p_k,    g_k);
    cudaGetSymbolAddress((void**)&p_v,    g_v);
    cudaGetSymbolAddress((void**)&p_ao,   g_ao);
    cudaGetSymbolAddress((void**)&p_xres, g_xres);
    cudaGetSymbolAddress((void**)&p_h2,   g_h2);
    cudaGetSymbolAddress((void**)&p_g,    g_g);
    cudaGetSymbolAddress((void**)&p_wa,   g_wa);
    cudaGetSymbolAddress((void**)&p_w1,   g_w1);
    cudaGetSymbolAddress((void**)&p_w2,   g_w2);

    cudaFuncSetAttribute(tf32_gemm<1, false, false>,
                         cudaFuncAttributeMaxDynamicSharedMemorySize, GSMEM_BYTES);
    cudaFuncSetAttribute(tf32_gemm<2, true, false>,
                         cudaFuncAttributeMaxDynamicSharedMemorySize, GSMEM_BYTES);
    cudaFuncSetAttribute(tf32_gemm<0, true, true>,
                         cudaFuncAttributeMaxDynamicSharedMemorySize, GSMEM_BYTES);
    cudaFuncSetAttribute(attn_tc_kernel,
                         cudaFuncAttributeMaxDynamicSharedMemorySize, AT_SMEM);

    // 0. pre-round all weights to tf32 in ONE launch
    {
        const int n4 = D_*3*D_/4 + D_*2*DFF_/4 + DFF_*D_/4;
        round3_tf32_kernel<<<(n4 + 255)/256, 256>>>(W_attn, p_wa, W1, p_w1, W2, p_w2);
    }
    // 1. LN1 (tf32-rounded output)
    ln_kernel<<<ROWS_, 128>>>(x_value, ln1_g, ln1_b, p_h);
    // 2. QKV GEMM with fused emb+RoPE+transpose epilogue -> Q/K/V directly
    tf32_gemm<1, false, false><<<dim3(12, ROWS_ / 128), 256, GSMEM_BYTES>>>(
        p_h, p_wa, nullptr, nullptr, nullptr, ROWS_, 3 * D_, D_,
        x_type, type_emb, seq_ord, p_q, p_k, p_v);
    // 3. causal flash attention (balanced q-tile pairs)
    attn_tc_kernel<<<dim3(4, H_, B_), 256, AT_SMEM>>>(p_q, p_k, p_v, p_ao);
    // 4. residual + LN2
    addres_ln2_kernel<<<ROWS_, 128>>>(x_value, p_ao, ln2_g, ln2_b, p_xres, p_h2);
    // 5. FFN GEMM1 + fused bias + SwiGLU epilogue -> g (tf32-rounded)
    tf32_gemm<2, true, false><<<dim3(16, ROWS_ / 128), 256, GSMEM_BYTES>>>(
        p_h2, p_w1, b1, nullptr, p_g, ROWS_, 2 * DFF_, D_);
    // 6. FFN GEMM2 + bias + residual -> out
    tf32_gemm<0, true, true><<<dim3(4, ROWS_ / 128), 256, GSMEM_BYTES>>>(
        p_g, p_w2, b2, p_xres, out, ROWS_, D_, DFF_);
}